// round 4
// baseline (speedup 1.0000x reference)
#include <cuda_runtime.h>
#include <stdint.h>

// Scratch (no device allocs allowed).
#define MAX_NODES 131072
__device__ int g_counts[MAX_NODES];
__device__ int g_is64;   // 1 if edge_index is int64, 0 if int32

// ---------------------------------------------------------------------------
// Kernel 0: detect edge-index dtype. For int64 data with values in
// [0, 2^31), every odd int32 word is 0. For int32 node indices, odd words
// are ~uniform in [0, 100000) -> essentially never all zero.
// ---------------------------------------------------------------------------
__global__ void detect_kernel(const int* __restrict__ ei32, long long n_words) {
    __shared__ int nz;
    if (threadIdx.x == 0) nz = 0;
    __syncthreads();
    // scan up to 4096 words: odd positions only
    long long limit = n_words < 4096 ? n_words : 4096;
    for (long long i = threadIdx.x * 2 + 1; i < limit; i += blockDim.x * 2) {
        if (ei32[i] != 0) atomicOr(&nz, 1);
    }
    __syncthreads();
    if (threadIdx.x == 0) g_is64 = (nz == 0) ? 1 : 0;
}

// ---------------------------------------------------------------------------
// Kernel 1: zero the output accumulator and the counts array.
// ---------------------------------------------------------------------------
__global__ void zero_kernel(float* __restrict__ out, long long n_out, int n_nodes) {
    long long i = (long long)blockIdx.x * blockDim.x + threadIdx.x;
    long long stride = (long long)gridDim.x * blockDim.x;
    for (long long j = i; j < n_out; j += stride) out[j] = 0.0f;
    for (long long j = i; j < n_nodes; j += stride) g_counts[j] = 0;
}

// ---------------------------------------------------------------------------
// Kernel 2: per-edge scatter. 16 threads per edge, float4 (4 feats) each.
//   messages = feat[src] + feat[dest]; atomically accumulate into out[dest].
// ---------------------------------------------------------------------------
__global__ void edge_kernel(const float* __restrict__ feat,
                            const void* __restrict__ ei_raw,
                            float* __restrict__ out,
                            long long E) {
    long long gid = (long long)blockIdx.x * blockDim.x + threadIdx.x;
    long long total = E * 16;
    if (gid >= total) return;

    long long e = gid >> 4;
    int c = (int)(gid & 15);

    int s, d;
    if (g_is64) {
        const long long* ei = (const long long*)ei_raw;
        s = (int)ei[e];
        d = (int)ei[E + e];
    } else {
        const int* ei = (const int*)ei_raw;
        s = ei[e];
        d = ei[E + e];
    }

    const float4* srow = (const float4*)(feat + (long long)s * 64);
    const float4* drow = (const float4*)(feat + (long long)d * 64);
    float4 a = __ldg(&srow[c]);
    float4 b = __ldg(&drow[c]);

    float* o = out + (long long)d * 64 + c * 4;
    atomicAdd(o + 0, a.x + b.x);
    atomicAdd(o + 1, a.y + b.y);
    atomicAdd(o + 2, a.z + b.z);
    atomicAdd(o + 3, a.w + b.w);

    if (c == 0) atomicAdd(&g_counts[d], 1);
}

// ---------------------------------------------------------------------------
// Kernel 3: finalize.  out = feat + out / max(count, 1)
// One thread per float4 (16 per node).
// ---------------------------------------------------------------------------
__global__ void final_kernel(const float* __restrict__ feat,
                             float* __restrict__ out,
                             int n_nodes) {
    int gid = blockIdx.x * blockDim.x + threadIdx.x;
    int total = n_nodes * 16;
    if (gid >= total) return;

    int v = gid >> 4;
    int cnt = g_counts[v];
    float inv = 1.0f / (float)max(cnt, 1);

    const float4* f4 = (const float4*)feat;
    float4* o4 = (float4*)out;
    float4 acc = o4[gid];
    float4 f = f4[gid];
    float4 r;
    r.x = f.x + acc.x * inv;
    r.y = f.y + acc.y * inv;
    r.z = f.z + acc.z * inv;
    r.w = f.w + acc.w * inv;
    o4[gid] = r;
}

extern "C" void kernel_launch(void* const* d_in, const int* in_sizes, int n_in,
                              void* d_out, int out_size) {
    const float* feat = (const float*)d_in[0];
    const void* ei = d_in[1];
    float* out = (float*)d_out;

    int n_nodes = in_sizes[0] / 64;            // 100000
    long long E = (long long)in_sizes[1] / 2;  // 1600000 (element count / 2 rows)
    long long n_out = (long long)n_nodes * 64;

    // Kernel 0: dtype sniff (int32 vs int64). If int32, the buffer has
    // 2*E int32 words; if int64 it has 4*E words when viewed as int32 —
    // scanning the first 4096 words is valid either way.
    detect_kernel<<<1, 256>>>((const int*)ei, 2 * E);

    // Kernel 1: zero accumulator + counts
    zero_kernel<<<2048, 256>>>(out, n_out, n_nodes);

    // Kernel 2: edge scatter
    {
        long long total = E * 16;
        int threads = 256;
        long long blocks = (total + threads - 1) / threads;
        edge_kernel<<<(unsigned int)blocks, threads>>>(feat, ei, out, E);
    }

    // Kernel 3: finalize
    {
        int total = n_nodes * 16;
        int threads = 256;
        int blocks = (total + threads - 1) / threads;
        final_kernel<<<blocks, threads>>>(feat, out, n_nodes);
    }
}

// round 5
// speedup vs baseline: 2.1309x; 2.1309x over previous
#include <cuda_runtime.h>
#include <stdint.h>

// Static scratch (no device allocs allowed).
#define MAX_NODES 131072
#define MAX_E     2000000
#define SCAN_T    1024

__device__ int g_counts[MAX_NODES];   // in-degree per node
__device__ int g_cursor[MAX_NODES];   // bucket fill cursor
__device__ int g_offsets[MAX_NODES];  // exclusive prefix of counts
__device__ int g_src[MAX_E];          // bucketed src ids (CSR adjacency)
__device__ int g_is64;                // edge index dtype flag

// ---------------------------------------------------------------------------
// Kernel 0: detect edge-index dtype (int64 vs int32). For int64 values in
// [0, 2^31) every odd int32 word is zero; for int32 node ids they are
// ~uniform in [0, N_NODES) and essentially never all zero.
// ---------------------------------------------------------------------------
__global__ void detect_kernel(const int* __restrict__ ei32, long long n_words) {
    __shared__ int nz;
    if (threadIdx.x == 0) nz = 0;
    __syncthreads();
    long long limit = n_words < 4096 ? n_words : 4096;
    for (long long i = threadIdx.x * 2 + 1; i < limit; i += blockDim.x * 2)
        if (ei32[i] != 0) atomicOr(&nz, 1);
    __syncthreads();
    if (threadIdx.x == 0) g_is64 = (nz == 0) ? 1 : 0;
}

// ---------------------------------------------------------------------------
// Kernel 1: zero counts + cursor.
// ---------------------------------------------------------------------------
__global__ void zero_kernel(int n_nodes) {
    int i = blockIdx.x * blockDim.x + threadIdx.x;
    if (i < n_nodes) { g_counts[i] = 0; g_cursor[i] = 0; }
}

// ---------------------------------------------------------------------------
// Kernel 2: in-degree histogram over dest row.
// ---------------------------------------------------------------------------
__global__ void count_kernel(const void* __restrict__ ei_raw, long long E) {
    long long e = (long long)blockIdx.x * blockDim.x + threadIdx.x;
    if (e >= E) return;
    int d;
    if (g_is64) d = (int)((const long long*)ei_raw)[E + e];
    else        d = ((const int*)ei_raw)[E + e];
    atomicAdd(&g_counts[d], 1);
}

// ---------------------------------------------------------------------------
// Kernel 3: single-block exclusive scan of counts -> offsets.
// Each thread owns a contiguous chunk; block-level Hillis-Steele on the
// per-thread sums, then serial sweep to write per-node offsets.
// ---------------------------------------------------------------------------
__global__ void scan_kernel(int n_nodes) {
    __shared__ int ssum[SCAN_T];
    int tid = threadIdx.x;
    int chunk = (n_nodes + SCAN_T - 1) / SCAN_T;
    int begin = tid * chunk;
    int end   = min(begin + chunk, n_nodes);

    int s = 0;
    for (int i = begin; i < end; i++) s += g_counts[i];
    ssum[tid] = s;
    __syncthreads();

    // inclusive scan
    for (int off = 1; off < SCAN_T; off <<= 1) {
        int v = (tid >= off) ? ssum[tid - off] : 0;
        __syncthreads();
        ssum[tid] += v;
        __syncthreads();
    }

    int run = ssum[tid] - s;   // exclusive prefix for this chunk
    for (int i = begin; i < end; i++) {
        g_offsets[i] = run;
        run += g_counts[i];
    }
}

// ---------------------------------------------------------------------------
// Kernel 4: scatter src ids into per-dest buckets.
// ---------------------------------------------------------------------------
__global__ void fill_kernel(const void* __restrict__ ei_raw, long long E) {
    long long e = (long long)blockIdx.x * blockDim.x + threadIdx.x;
    if (e >= E) return;
    int s, d;
    if (g_is64) {
        const long long* ei = (const long long*)ei_raw;
        s = (int)ei[e];
        d = (int)ei[E + e];
    } else {
        const int* ei = (const int*)ei_raw;
        s = ei[e];
        d = ei[E + e];
    }
    int pos = g_offsets[d] + atomicAdd(&g_cursor[d], 1);
    g_src[pos] = s;
}

// ---------------------------------------------------------------------------
// Kernel 5: aggregate. One warp per dest node, float2 per lane (64 feats).
//   out[d] = feat[d] + (sum_src feat[src] + deg*feat[d]) / max(deg,1)
// Gathers are coalesced 256B rows, hitting L2 (features fit in L2).
// ---------------------------------------------------------------------------
__global__ void aggregate_kernel(const float* __restrict__ feat,
                                 float* __restrict__ out,
                                 int n_nodes) {
    int warp = (blockIdx.x * blockDim.x + threadIdx.x) >> 5;
    int lane = threadIdx.x & 31;
    if (warp >= n_nodes) return;

    int v   = warp;
    int cnt = g_counts[v];
    int off = g_offsets[v];

    const float2* f2 = (const float2*)feat;
    float2 acc = make_float2(0.0f, 0.0f);

    int k = 0;
    // unroll x4 for memory-level parallelism
    for (; k + 4 <= cnt; k += 4) {
        int s0 = g_src[off + k + 0];
        int s1 = g_src[off + k + 1];
        int s2 = g_src[off + k + 2];
        int s3 = g_src[off + k + 3];
        float2 x0 = __ldg(&f2[(long long)s0 * 32 + lane]);
        float2 x1 = __ldg(&f2[(long long)s1 * 32 + lane]);
        float2 x2 = __ldg(&f2[(long long)s2 * 32 + lane]);
        float2 x3 = __ldg(&f2[(long long)s3 * 32 + lane]);
        acc.x += x0.x + x1.x + x2.x + x3.x;
        acc.y += x0.y + x1.y + x2.y + x3.y;
    }
    for (; k < cnt; k++) {
        int s0 = g_src[off + k];
        float2 x0 = __ldg(&f2[(long long)s0 * 32 + lane]);
        acc.x += x0.x;
        acc.y += x0.y;
    }

    float2 fd = __ldg(&f2[(long long)v * 32 + lane]);
    float fc  = (float)cnt;
    float inv = 1.0f / (float)max(cnt, 1);

    float2 r;
    r.x = fd.x + (acc.x + fc * fd.x) * inv;
    r.y = fd.y + (acc.y + fc * fd.y) * inv;
    ((float2*)out)[(long long)v * 32 + lane] = r;
}

extern "C" void kernel_launch(void* const* d_in, const int* in_sizes, int n_in,
                              void* d_out, int out_size) {
    const float* feat = (const float*)d_in[0];
    const void* ei = d_in[1];
    float* out = (float*)d_out;

    int n_nodes = in_sizes[0] / 64;            // 100000
    long long E = (long long)in_sizes[1] / 2;  // 1600000

    detect_kernel<<<1, 256>>>((const int*)ei, 2 * E);

    zero_kernel<<<(n_nodes + 255) / 256, 256>>>(n_nodes);

    {
        int threads = 256;
        long long blocks = (E + threads - 1) / threads;
        count_kernel<<<(unsigned int)blocks, threads>>>(ei, E);
    }

    scan_kernel<<<1, SCAN_T>>>(n_nodes);

    {
        int threads = 256;
        long long blocks = (E + threads - 1) / threads;
        fill_kernel<<<(unsigned int)blocks, threads>>>(ei, E);
    }

    {
        long long total = (long long)n_nodes * 32;   // one warp per node
        int threads = 256;
        long long blocks = (total + threads - 1) / threads;
        aggregate_kernel<<<(unsigned int)blocks, threads>>>(feat, out, n_nodes);
    }
}

// round 7
// speedup vs baseline: 4.5002x; 2.1119x over previous
#include <cuda_runtime.h>
#include <stdint.h>

// Static scratch (no device allocs allowed).
#define MAX_NODES 131072
#define MAX_E     2000000
#define SCAN_B    1024                 // scan block size (threads = elems/block)
#define MAX_SCAN_BLOCKS 128

__device__ int g_counts[MAX_NODES];   // in-degree per node
__device__ int g_cursor[MAX_NODES];   // bucket fill cursor (seeded to offsets)
__device__ int g_offsets[MAX_NODES];  // exclusive prefix of counts
__device__ int g_bsum[MAX_SCAN_BLOCKS];   // per-block sums
__device__ int g_bpre[MAX_SCAN_BLOCKS];   // exclusive prefix of block sums
__device__ int g_src[MAX_E];          // bucketed src ids (CSR adjacency)
__device__ int g_is64;                // edge index dtype flag

// ---------------------------------------------------------------------------
// Kernel 0: detect edge-index dtype (int64 vs int32).
// ---------------------------------------------------------------------------
__global__ void detect_kernel(const int* __restrict__ ei32, long long n_words) {
    __shared__ int nz;
    if (threadIdx.x == 0) nz = 0;
    __syncthreads();
    long long limit = n_words < 4096 ? n_words : 4096;
    for (long long i = threadIdx.x * 2 + 1; i < limit; i += blockDim.x * 2)
        if (ei32[i] != 0) atomicOr(&nz, 1);
    __syncthreads();
    if (threadIdx.x == 0) g_is64 = (nz == 0) ? 1 : 0;
}

// ---------------------------------------------------------------------------
// Kernel 1: zero counts.
// ---------------------------------------------------------------------------
__global__ void zero_kernel(int n_nodes) {
    int i = blockIdx.x * blockDim.x + threadIdx.x;
    if (i < n_nodes) g_counts[i] = 0;
}

// ---------------------------------------------------------------------------
// Kernel 2: in-degree histogram over dest row.
// ---------------------------------------------------------------------------
__global__ void count_kernel(const void* __restrict__ ei_raw, long long E) {
    long long e = (long long)blockIdx.x * blockDim.x + threadIdx.x;
    if (e >= E) return;
    int d;
    if (g_is64) d = (int)((const long long*)ei_raw)[E + e];
    else        d = ((const int*)ei_raw)[E + e];
    atomicAdd(&g_counts[d], 1);
}

// ---------------------------------------------------------------------------
// Scan stage 1: per-block sums of counts (SCAN_B elems per block).
// ---------------------------------------------------------------------------
__global__ void scan1_kernel(int n_nodes) {
    __shared__ int wsum[32];
    int i = blockIdx.x * SCAN_B + threadIdx.x;
    int c = (i < n_nodes) ? g_counts[i] : 0;

    // warp reduce
    #pragma unroll
    for (int o = 16; o > 0; o >>= 1)
        c += __shfl_down_sync(0xFFFFFFFFu, c, o);
    int wid = threadIdx.x >> 5, lane = threadIdx.x & 31;
    if (lane == 0) wsum[wid] = c;
    __syncthreads();
    if (wid == 0) {
        int v = (lane < SCAN_B / 32) ? wsum[lane] : 0;
        #pragma unroll
        for (int o = 16; o > 0; o >>= 1)
            v += __shfl_down_sync(0xFFFFFFFFu, v, o);
        if (lane == 0) g_bsum[blockIdx.x] = v;
    }
}

// ---------------------------------------------------------------------------
// Scan stage 2: exclusive scan of block sums (nblocks <= 128, one block).
// ---------------------------------------------------------------------------
__global__ void scan2_kernel(int nblocks) {
    __shared__ int s[MAX_SCAN_BLOCKS];
    int t = threadIdx.x;
    s[t] = (t < nblocks) ? g_bsum[t] : 0;
    __syncthreads();
    // inclusive Hillis-Steele over 128 entries
    #pragma unroll
    for (int o = 1; o < MAX_SCAN_BLOCKS; o <<= 1) {
        int v = (t >= o) ? s[t - o] : 0;
        __syncthreads();
        s[t] += v;
        __syncthreads();
    }
    if (t < nblocks) g_bpre[t] = s[t] - g_bsum[t];  // exclusive
}

// ---------------------------------------------------------------------------
// Scan stage 3: block-level exclusive scan + carry; write offsets and seed
// cursor with the same value.
// ---------------------------------------------------------------------------
__global__ void scan3_kernel(int n_nodes) {
    __shared__ int wpre[32];
    int i = blockIdx.x * SCAN_B + threadIdx.x;
    int c = (i < n_nodes) ? g_counts[i] : 0;
    int wid = threadIdx.x >> 5, lane = threadIdx.x & 31;

    // intra-warp inclusive scan
    int inc = c;
    #pragma unroll
    for (int o = 1; o < 32; o <<= 1) {
        int v = __shfl_up_sync(0xFFFFFFFFu, inc, o);
        if (lane >= o) inc += v;
    }
    if (lane == 31) wpre[wid] = inc;
    __syncthreads();
    if (wid == 0) {
        int v = (lane < SCAN_B / 32) ? wpre[lane] : 0;
        int winc = v;
        #pragma unroll
        for (int o = 1; o < 32; o <<= 1) {
            int u = __shfl_up_sync(0xFFFFFFFFu, winc, o);
            if (lane >= o) winc += u;
        }
        wpre[lane] = winc - v;   // exclusive warp prefix
    }
    __syncthreads();

    if (i < n_nodes) {
        int off = g_bpre[blockIdx.x] + wpre[wid] + (inc - c);
        g_offsets[i] = off;
        g_cursor[i]  = off;
    }
}

// ---------------------------------------------------------------------------
// Kernel 4: scatter src ids into per-dest buckets.
// ---------------------------------------------------------------------------
__global__ void fill_kernel(const void* __restrict__ ei_raw, long long E) {
    long long e = (long long)blockIdx.x * blockDim.x + threadIdx.x;
    if (e >= E) return;
    int s, d;
    if (g_is64) {
        const long long* ei = (const long long*)ei_raw;
        s = (int)ei[e];
        d = (int)ei[E + e];
    } else {
        const int* ei = (const int*)ei_raw;
        s = ei[e];
        d = ei[E + e];
    }
    int pos = atomicAdd(&g_cursor[d], 1);
    g_src[pos] = s;
}

// ---------------------------------------------------------------------------
// Kernel 5: aggregate. One warp per dest node, float2 per lane (64 feats).
//   out[d] = feat[d] + (sum_src feat[src] + deg*feat[d]) / max(deg,1)
// ---------------------------------------------------------------------------
__global__ void aggregate_kernel(const float* __restrict__ feat,
                                 float* __restrict__ out,
                                 int n_nodes) {
    int warp = (blockIdx.x * blockDim.x + threadIdx.x) >> 5;
    int lane = threadIdx.x & 31;
    if (warp >= n_nodes) return;

    int v   = warp;
    int cnt = g_counts[v];
    int off = g_offsets[v];

    const float2* f2 = (const float2*)feat;
    float2 acc = make_float2(0.0f, 0.0f);

    int k = 0;
    for (; k + 4 <= cnt; k += 4) {
        int s0 = g_src[off + k + 0];
        int s1 = g_src[off + k + 1];
        int s2 = g_src[off + k + 2];
        int s3 = g_src[off + k + 3];
        float2 x0 = __ldg(&f2[(long long)s0 * 32 + lane]);
        float2 x1 = __ldg(&f2[(long long)s1 * 32 + lane]);
        float2 x2 = __ldg(&f2[(long long)s2 * 32 + lane]);
        float2 x3 = __ldg(&f2[(long long)s3 * 32 + lane]);
        acc.x += x0.x + x1.x + x2.x + x3.x;
        acc.y += x0.y + x1.y + x2.y + x3.y;
    }
    for (; k < cnt; k++) {
        int s0 = g_src[off + k];
        float2 x0 = __ldg(&f2[(long long)s0 * 32 + lane]);
        acc.x += x0.x;
        acc.y += x0.y;
    }

    float2 fd = __ldg(&f2[(long long)v * 32 + lane]);
    float fc  = (float)cnt;
    float inv = 1.0f / (float)max(cnt, 1);

    float2 r;
    r.x = fd.x + (acc.x + fc * fd.x) * inv;
    r.y = fd.y + (acc.y + fc * fd.y) * inv;
    ((float2*)out)[(long long)v * 32 + lane] = r;
}

extern "C" void kernel_launch(void* const* d_in, const int* in_sizes, int n_in,
                              void* d_out, int out_size) {
    const float* feat = (const float*)d_in[0];
    const void* ei = d_in[1];
    float* out = (float*)d_out;

    int n_nodes = in_sizes[0] / 64;            // 100000
    long long E = (long long)in_sizes[1] / 2;  // 1600000

    int nscan = (n_nodes + SCAN_B - 1) / SCAN_B;   // 98 blocks

    detect_kernel<<<1, 256>>>((const int*)ei, 2 * E);
    zero_kernel<<<(n_nodes + 255) / 256, 256>>>(n_nodes);

    {
        int threads = 256;
        long long blocks = (E + threads - 1) / threads;
        count_kernel<<<(unsigned int)blocks, threads>>>(ei, E);
    }

    scan1_kernel<<<nscan, SCAN_B>>>(n_nodes);
    scan2_kernel<<<1, MAX_SCAN_BLOCKS>>>(nscan);
    scan3_kernel<<<nscan, SCAN_B>>>(n_nodes);

    {
        int threads = 256;
        long long blocks = (E + threads - 1) / threads;
        fill_kernel<<<(unsigned int)blocks, threads>>>(ei, E);
    }

    {
        long long total = (long long)n_nodes * 32;   // one warp per node
        int threads = 256;
        long long blocks = (total + threads - 1) / threads;
        aggregate_kernel<<<(unsigned int)blocks, threads>>>(feat, out, n_nodes);
    }
}

// round 8
// speedup vs baseline: 6.2127x; 1.3805x over previous
#include <cuda_runtime.h>
#include <stdint.h>

// Static scratch (no device allocs allowed).
#define MAX_NODES 131072
#define BUCKET_CAP 64
#define MAX_SPILL 8192

__device__ int g_cursor[MAX_NODES];                 // per-node fill cursor == in-degree
__device__ int g_bucket[MAX_NODES * BUCKET_CAP];    // src ids, 64 slots per node (25.6+ MB)
__device__ int g_spill_src[MAX_SPILL];
__device__ int g_spill_dst[MAX_SPILL];
__device__ int g_spill_n;
__device__ int g_is64;                              // edge index dtype flag

// ---------------------------------------------------------------------------
// Kernel 1: zero cursors + spill counter; block 0 also sniffs the edge-index
// dtype (int64 values < 2^31 have zero odd int32 words; int32 node ids are
// ~uniform in [0,1e5) and essentially never all zero over 2048 samples).
// ---------------------------------------------------------------------------
__global__ void init_kernel(const int* __restrict__ ei32, long long n_words,
                            int n_nodes) {
    int i = blockIdx.x * blockDim.x + threadIdx.x;
    if (i < n_nodes) g_cursor[i] = 0;
    if (i == 0) g_spill_n = 0;

    if (blockIdx.x == 0) {
        __shared__ int nz;
        if (threadIdx.x == 0) nz = 0;
        __syncthreads();
        long long limit = n_words < 4096 ? n_words : 4096;
        for (long long j = threadIdx.x * 2 + 1; j < limit; j += blockDim.x * 2)
            if (ei32[j] != 0) atomicOr(&nz, 1);
        __syncthreads();
        if (threadIdx.x == 0) g_is64 = (nz == 0) ? 1 : 0;
    }
}

// ---------------------------------------------------------------------------
// Kernel 2: single edge pass — scatter src ids into fixed-capacity buckets.
// Overflow (vanishingly rare) goes to the spill list.
// ---------------------------------------------------------------------------
__global__ void fill_kernel(const void* __restrict__ ei_raw, long long E) {
    long long e = (long long)blockIdx.x * blockDim.x + threadIdx.x;
    if (e >= E) return;
    int s, d;
    if (g_is64) {
        const long long* ei = (const long long*)ei_raw;
        s = (int)ei[e];
        d = (int)ei[E + e];
    } else {
        const int* ei = (const int*)ei_raw;
        s = ei[e];
        d = ei[E + e];
    }
    int pos = atomicAdd(&g_cursor[d], 1);
    if (pos < BUCKET_CAP) {
        g_bucket[(long long)d * BUCKET_CAP + pos] = s;
    } else {
        int sp = atomicAdd(&g_spill_n, 1);
        if (sp < MAX_SPILL) { g_spill_src[sp] = s; g_spill_dst[sp] = d; }
    }
}

// ---------------------------------------------------------------------------
// Kernel 3: aggregate. One warp per dest node, float2 per lane (64 feats).
//   out[d] = feat[d] + (sum_src feat[src] + deg*feat[d]) / max(deg,1)
// deg = true in-degree (cursor), so the deg*feat[d] term covers spilled
// edges too; spill kernel only adds the missing feat[src]*inv parts.
// ---------------------------------------------------------------------------
__global__ void aggregate_kernel(const float* __restrict__ feat,
                                 float* __restrict__ out,
                                 int n_nodes) {
    int warp = (blockIdx.x * blockDim.x + threadIdx.x) >> 5;
    int lane = threadIdx.x & 31;
    if (warp >= n_nodes) return;

    int v   = warp;
    int deg = g_cursor[v];
    int cnt = min(deg, BUCKET_CAP);
    const int* bucket = g_bucket + (long long)v * BUCKET_CAP;

    const float2* f2 = (const float2*)feat;
    float2 acc = make_float2(0.0f, 0.0f);

    int k = 0;
    for (; k + 8 <= cnt; k += 8) {
        int sid[8];
        #pragma unroll
        for (int u = 0; u < 8; u++) sid[u] = bucket[k + u];
        #pragma unroll
        for (int u = 0; u < 8; u++) {
            float2 x = __ldg(&f2[(long long)sid[u] * 32 + lane]);
            acc.x += x.x;
            acc.y += x.y;
        }
    }
    for (; k < cnt; k++) {
        int s0 = bucket[k];
        float2 x0 = __ldg(&f2[(long long)s0 * 32 + lane]);
        acc.x += x0.x;
        acc.y += x0.y;
    }

    float2 fd = __ldg(&f2[(long long)v * 32 + lane]);
    float fc  = (float)deg;
    float inv = 1.0f / (float)max(deg, 1);

    float2 r;
    r.x = fd.x + (acc.x + fc * fd.x) * inv;
    r.y = fd.y + (acc.y + fc * fd.y) * inv;
    ((float2*)out)[(long long)v * 32 + lane] = r;
}

// ---------------------------------------------------------------------------
// Kernel 4: spill fixup (normally 0 entries). Adds feat[src]*inv_deg into out.
// ---------------------------------------------------------------------------
__global__ void spill_kernel(const float* __restrict__ feat,
                             float* __restrict__ out) {
    int n = g_spill_n;
    if (n > MAX_SPILL) n = MAX_SPILL;
    // each entry handled by 64 threads (one per feature)
    for (int idx = blockIdx.x * blockDim.x + threadIdx.x;
         idx < n * 64;
         idx += gridDim.x * blockDim.x) {
        int i = idx >> 6;
        int c = idx & 63;
        int s = g_spill_src[i];
        int d = g_spill_dst[i];
        float inv = 1.0f / (float)max(g_cursor[d], 1);
        atomicAdd(&out[(long long)d * 64 + c], feat[(long long)s * 64 + c] * inv);
    }
}

extern "C" void kernel_launch(void* const* d_in, const int* in_sizes, int n_in,
                              void* d_out, int out_size) {
    const float* feat = (const float*)d_in[0];
    const void* ei = d_in[1];
    float* out = (float*)d_out;

    int n_nodes = in_sizes[0] / 64;            // 100000
    long long E = (long long)in_sizes[1] / 2;  // 1600000

    init_kernel<<<(n_nodes + 255) / 256, 256>>>((const int*)ei, 2 * E, n_nodes);

    {
        int threads = 256;
        long long blocks = (E + threads - 1) / threads;
        fill_kernel<<<(unsigned int)blocks, threads>>>(ei, E);
    }

    {
        long long total = (long long)n_nodes * 32;   // one warp per node
        int threads = 256;
        long long blocks = (total + threads - 1) / threads;
        aggregate_kernel<<<(unsigned int)blocks, threads>>>(feat, out, n_nodes);
    }

    spill_kernel<<<64, 256>>>(feat, out);
}